// round 3
// baseline (speedup 1.0000x reference)
#include <cuda_runtime.h>
#include <cstring>

// Fused JPEG round-trip. 8 lanes per 8x8 block (lane = row), shuffle transposes,
// chroma U+V packed into f32x2 (Blackwell FFMA2 path). No smem staging.
// Input : d_in[0] = float32 [1,3,2048,2048]; Output: float32 [1,3*2048*2048]

#define IMG_W  2048
#define IMG_H  2048
#define PLANE  (IMG_W * IMG_H)

// DCT basis constants (fp32 round of the reference matrix entries)
#define C1 0.4903926402f
#define C2 0.4619397663f
#define C3 0.4157348062f
#define C4 0.3535533906f
#define C5 0.2777851165f
#define C6 0.1913417162f
#define C7 0.0975451610f

// Quant tables, luma then chroma (Q=50 -> s=1)
__constant__ float cQf[128] = {
    16,11,10,16,24,40,51,61,  12,12,14,19,26,58,60,55,
    14,13,16,24,40,57,69,56,  14,17,22,29,51,87,80,62,
    18,22,37,56,68,109,103,77, 24,35,55,64,81,104,113,92,
    49,64,78,87,103,121,120,101, 72,92,95,98,112,100,103,99,
    17,18,24,47,99,99,99,99,  18,21,26,66,99,99,99,99,
    24,26,56,99,99,99,99,99,  47,66,99,99,99,99,99,99,
    99,99,99,99,99,99,99,99,  99,99,99,99,99,99,99,99,
    99,99,99,99,99,99,99,99,  99,99,99,99,99,99,99,99 };
__constant__ float cRQf[128] = {
    1.f/16,1.f/11,1.f/10,1.f/16,1.f/24,1.f/40,1.f/51,1.f/61,
    1.f/12,1.f/12,1.f/14,1.f/19,1.f/26,1.f/58,1.f/60,1.f/55,
    1.f/14,1.f/13,1.f/16,1.f/24,1.f/40,1.f/57,1.f/69,1.f/56,
    1.f/14,1.f/17,1.f/22,1.f/29,1.f/51,1.f/87,1.f/80,1.f/62,
    1.f/18,1.f/22,1.f/37,1.f/56,1.f/68,1.f/109,1.f/103,1.f/77,
    1.f/24,1.f/35,1.f/55,1.f/64,1.f/81,1.f/104,1.f/113,1.f/92,
    1.f/49,1.f/64,1.f/78,1.f/87,1.f/103,1.f/121,1.f/120,1.f/101,
    1.f/72,1.f/92,1.f/95,1.f/98,1.f/112,1.f/100,1.f/103,1.f/99,
    1.f/17,1.f/18,1.f/24,1.f/47,1.f/99,1.f/99,1.f/99,1.f/99,
    1.f/18,1.f/21,1.f/26,1.f/66,1.f/99,1.f/99,1.f/99,1.f/99,
    1.f/24,1.f/26,1.f/56,1.f/99,1.f/99,1.f/99,1.f/99,1.f/99,
    1.f/47,1.f/66,1.f/99,1.f/99,1.f/99,1.f/99,1.f/99,1.f/99,
    1.f/99,1.f/99,1.f/99,1.f/99,1.f/99,1.f/99,1.f/99,1.f/99,
    1.f/99,1.f/99,1.f/99,1.f/99,1.f/99,1.f/99,1.f/99,1.f/99,
    1.f/99,1.f/99,1.f/99,1.f/99,1.f/99,1.f/99,1.f/99,1.f/99,
    1.f/99,1.f/99,1.f/99,1.f/99,1.f/99,1.f/99,1.f/99,1.f/99 };

// inv(W)
#define IW01 (-1.2189e-6f)
#define IW02  1.4019996f
#define IW11 (-0.34413570f)
#define IW12 (-0.71413614f)
#define IW21  1.7720001f
#define IW22  4.0630e-7f
#define MEAN0 0.49137255f
#define MEAN1 0.48235294f
#define MEAN2 0.44666666f
#define ISTD0 4.04761905f
#define ISTD1 4.10628019f
#define ISTD2 3.82308846f

typedef unsigned long long ull;

// ---- packed f32x2 helpers ----
__device__ __forceinline__ ull pk(float lo, float hi) {
    float2 t = make_float2(lo, hi); ull r; memcpy(&r, &t, 8); return r;
}
__device__ __forceinline__ ull pk1(float x) { return pk(x, x); }
__device__ __forceinline__ void unpk(ull a, float& lo, float& hi) {
    float2 t; memcpy(&t, &a, 8); lo = t.x; hi = t.y;
}
__device__ __forceinline__ ull padd(ull a, ull b) {
    ull r; asm("add.rn.f32x2 %0,%1,%2;" : "=l"(r) : "l"(a), "l"(b)); return r;
}
__device__ __forceinline__ ull pmul(ull a, ull b) {
    ull r; asm("mul.rn.f32x2 %0,%1,%2;" : "=l"(r) : "l"(a), "l"(b)); return r;
}
__device__ __forceinline__ ull pfma(ull a, ull b, ull c) {
    ull r; asm("fma.rn.f32x2 %0,%1,%2,%3;" : "=l"(r) : "l"(a), "l"(b), "l"(c)); return r;
}
__device__ __forceinline__ ull psub(ull a, ull b) { return pfma(b, pk1(-1.0f), a); } // exact a-b

// ---- scalar 8-pt transforms ----
__device__ __forceinline__ void fdct8(float v[8]) {
    float e0=v[0]+v[7], e1=v[1]+v[6], e2=v[2]+v[5], e3=v[3]+v[4];
    float o0=v[0]-v[7], o1=v[1]-v[6], o2=v[2]-v[5], o3=v[3]-v[4];
    float s03=e0+e3, s12=e1+e2, d03=e0-e3, d12=e1-e2;
    v[0]=C4*(s03+s12);
    v[4]=C4*(s03-s12);
    v[2]=fmaf(C2,d03, C6*d12);
    v[6]=fmaf(C6,d03,-C2*d12);
    v[1]=fmaf(C1,o0,fmaf( C3,o1,fmaf( C5,o2, C7*o3)));
    v[3]=fmaf(C3,o0,fmaf(-C7,o1,fmaf(-C1,o2,-C5*o3)));
    v[5]=fmaf(C5,o0,fmaf(-C1,o1,fmaf( C7,o2, C3*o3)));
    v[7]=fmaf(C7,o0,fmaf(-C5,o1,fmaf( C3,o2,-C1*o3)));
}
__device__ __forceinline__ void idct8(float v[8]) {
    float sp=C4*(v[0]+v[4]), sm=C4*(v[0]-v[4]);
    float t1=fmaf(C2,v[2], C6*v[6]);
    float t2=fmaf(C6,v[2],-C2*v[6]);
    float E0=sp+t1, E1=sm+t2, E2=sm-t2, E3=sp-t1;
    float O0=fmaf(C1,v[1],fmaf( C3,v[3],fmaf( C5,v[5], C7*v[7])));
    float O1=fmaf(C3,v[1],fmaf(-C7,v[3],fmaf(-C1,v[5],-C5*v[7])));
    float O2=fmaf(C5,v[1],fmaf(-C1,v[3],fmaf( C7,v[5], C3*v[7])));
    float O3=fmaf(C7,v[1],fmaf(-C5,v[3],fmaf( C3,v[5],-C1*v[7])));
    v[0]=E0+O0; v[7]=E0-O0;
    v[1]=E1+O1; v[6]=E1-O1;
    v[2]=E2+O2; v[5]=E2-O2;
    v[3]=E3+O3; v[4]=E3-O3;
}

// ---- packed 8-pt transforms (bit-identical per half) ----
__device__ __forceinline__ void fdct8p(ull v[8]) {
    ull e0=padd(v[0],v[7]), e1=padd(v[1],v[6]), e2=padd(v[2],v[5]), e3=padd(v[3],v[4]);
    ull o0=psub(v[0],v[7]), o1=psub(v[1],v[6]), o2=psub(v[2],v[5]), o3=psub(v[3],v[4]);
    ull s03=padd(e0,e3), s12=padd(e1,e2), d03=psub(e0,e3), d12=psub(e1,e2);
    v[0]=pmul(pk1(C4), padd(s03,s12));
    v[4]=pmul(pk1(C4), psub(s03,s12));
    v[2]=pfma(pk1(C2),d03, pmul(pk1( C6),d12));
    v[6]=pfma(pk1(C6),d03, pmul(pk1(-C2),d12));
    v[1]=pfma(pk1(C1),o0, pfma(pk1( C3),o1, pfma(pk1( C5),o2, pmul(pk1( C7),o3))));
    v[3]=pfma(pk1(C3),o0, pfma(pk1(-C7),o1, pfma(pk1(-C1),o2, pmul(pk1(-C5),o3))));
    v[5]=pfma(pk1(C5),o0, pfma(pk1(-C1),o1, pfma(pk1( C7),o2, pmul(pk1( C3),o3))));
    v[7]=pfma(pk1(C7),o0, pfma(pk1(-C5),o1, pfma(pk1( C3),o2, pmul(pk1(-C1),o3))));
}
__device__ __forceinline__ void idct8p(ull v[8]) {
    ull sp=pmul(pk1(C4), padd(v[0],v[4]));
    ull sm=pmul(pk1(C4), psub(v[0],v[4]));
    ull t1=pfma(pk1(C2),v[2], pmul(pk1( C6),v[6]));
    ull t2=pfma(pk1(C6),v[2], pmul(pk1(-C2),v[6]));
    ull E0=padd(sp,t1), E1=padd(sm,t2), E2=psub(sm,t2), E3=psub(sp,t1);
    ull O0=pfma(pk1(C1),v[1], pfma(pk1( C3),v[3], pfma(pk1( C5),v[5], pmul(pk1( C7),v[7]))));
    ull O1=pfma(pk1(C3),v[1], pfma(pk1(-C7),v[3], pfma(pk1(-C1),v[5], pmul(pk1(-C5),v[7]))));
    ull O2=pfma(pk1(C5),v[1], pfma(pk1(-C1),v[3], pfma(pk1( C7),v[5], pmul(pk1( C3),v[7]))));
    ull O3=pfma(pk1(C7),v[1], pfma(pk1(-C5),v[3], pfma(pk1( C3),v[5], pmul(pk1(-C1),v[7]))));
    v[0]=padd(E0,O0); v[7]=psub(E0,O0);
    v[1]=padd(E1,O1); v[6]=psub(E1,O1);
    v[2]=padd(E2,O2); v[5]=psub(E2,O2);
    v[3]=padd(E3,O3); v[4]=psub(E3,O3);
}

// ---- 8x8 transpose across 8 lanes via xor-butterfly shuffles ----
// lane holds row r (r = lane>>2); partner lane mask = m<<2 keeps group (lane&3)
template <typename T>
__device__ __forceinline__ void xpose8(T v[8], int r) {
    #pragma unroll
    for (int m = 1; m < 8; m <<= 1) {
        bool up = (r & m) != 0;
        #pragma unroll
        for (int c0 = 0; c0 < 8; ++c0) {
            if (c0 & m) continue;
            int c1 = c0 | m;
            T send = up ? v[c0] : v[c1];
            T got = __shfl_xor_sync(0xffffffffu, send, m << 2);
            if (up) v[c0] = got; else v[c1] = got;
        }
    }
}

__global__ __launch_bounds__(256)
void jpeg_roundtrip_kernel(const float* __restrict__ in, float* __restrict__ out)
{
    __shared__ float qsm[128], rqsm[128];
    const int tid = threadIdx.x;
    if (tid < 128) { qsm[tid] = cQf[tid]; rqsm[tid] = cRQf[tid]; }
    __syncthreads();

    const int lane = tid & 31;
    const int warp = tid >> 5;
    const int r    = lane >> 2;      // row within the 8x8 block
    const int g    = lane & 3;       // group within warp
    const int x0   = blockIdx.x * 256 + (warp * 4 + g) * 8;
    const int y    = blockIdx.y * 8 + r;
    const long base = (long)y * IMG_W + x0;

    // ---- load RGB row, forward color ----
    float vY[8];
    ull   pUV[8];
    {
        const float4 Ra = *(const float4*)(in + base);
        const float4 Rb = *(const float4*)(in + base + 4);
        const float4 Ga = *(const float4*)(in + base + PLANE);
        const float4 Gb = *(const float4*)(in + base + PLANE + 4);
        const float4 Ba = *(const float4*)(in + base + 2*PLANE);
        const float4 Bb = *(const float4*)(in + base + 2*PLANE + 4);
        float R[8] = {Ra.x,Ra.y,Ra.z,Ra.w, Rb.x,Rb.y,Rb.z,Rb.w};
        float G[8] = {Ga.x,Ga.y,Ga.z,Ga.w, Gb.x,Gb.y,Gb.z,Gb.w};
        float B[8] = {Ba.x,Ba.y,Ba.z,Ba.w, Bb.x,Bb.y,Bb.z,Bb.w};
        #pragma unroll
        for (int k = 0; k < 8; ++k) {
            vY[k] = 0.299f*R[k] + 0.587f*G[k] + 0.114f*B[k];
            pUV[k] = pfma(pk1(R[k]), pk(-0.168736f, 0.5f),
                     pfma(pk1(G[k]), pk(-0.331264f, -0.418688f),
                     pfma(pk1(B[k]), pk(0.5f, -0.081312f), pk1(128.0f))));
        }
    }

    // ---- luma pipeline ----
    fdct8(vY); xpose8(vY, r); fdct8(vY);
    #pragma unroll
    for (int c = 0; c < 8; ++c) {      // lane r holds T1[c][r] at index c
        float q  = qsm[c*8 + r];
        float rq = rqsm[c*8 + r];
        float sv = vY[c];
        float d  = sv * rq;
        float rn = rintf(d);
        float e  = fmaf(-rn, q, sv) * rq;
        vY[c]    = fmaf(e*e, e, rn) * q;
    }
    idct8(vY); xpose8(vY, r); idct8(vY);

    // ---- chroma pipeline (U,V packed) ----
    fdct8p(pUV); xpose8(pUV, r); fdct8p(pUV);
    #pragma unroll
    for (int c = 0; c < 8; ++c) {
        float q  = qsm[64 + c*8 + r];
        float rq = rqsm[64 + c*8 + r];
        float lo, hi; unpk(pUV[c], lo, hi);
        float d0 = lo * rq, d1 = hi * rq;
        float r0 = rintf(d0), r1 = rintf(d1);
        float e0 = fmaf(-r0, q, lo) * rq;
        float e1 = fmaf(-r1, q, hi) * rq;
        lo = fmaf(e0*e0, e0, r0) * q;
        hi = fmaf(e1*e1, e1, r1) * q;
        pUV[c] = pk(lo, hi);
    }
    idct8p(pUV); xpose8(pUV, r); idct8p(pUV);

    // ---- inverse color + normalize + store ----
    #pragma unroll
    for (int h = 0; h < 2; ++h) {
        float4 Ro, Go, Bo;
        #pragma unroll
        for (int k = 0; k < 4; ++k) {
            int c = h*4 + k;
            float yv = vY[c];
            float u, v; unpk(pUV[c], u, v);
            u -= 128.0f; v -= 128.0f;
            ull rg = pfma(pk1(u), pk(IW01, IW11),
                     pfma(pk1(v), pk(IW02, IW12), pk1(yv)));
            float Bv = fmaf(IW21, u, fmaf(IW22, v, yv));
            float Rv, Gv; unpk(rg, Rv, Gv);
            ((float*)&Ro)[k] = (Rv * (1.0f/255.0f) - MEAN0) * ISTD0;
            ((float*)&Go)[k] = (Gv * (1.0f/255.0f) - MEAN1) * ISTD1;
            ((float*)&Bo)[k] = (Bv * (1.0f/255.0f) - MEAN2) * ISTD2;
        }
        *(float4*)(out + base + h*4)             = Ro;
        *(float4*)(out + base + PLANE + h*4)     = Go;
        *(float4*)(out + base + 2*PLANE + h*4)   = Bo;
    }
}

extern "C" void kernel_launch(void* const* d_in, const int* in_sizes, int n_in,
                              void* d_out, int out_size)
{
    const float* in = (const float*)d_in[0];
    float* out = (float*)d_out;
    dim3 grid(IMG_W / 256, IMG_H / 8);
    jpeg_roundtrip_kernel<<<grid, 256>>>(in, out);
}